// round 12
// baseline (speedup 1.0000x reference)
#include <cuda_runtime.h>
#include <stdint.h>

#define HH 512
#define WW 512
#define NB 2
#define NC 4
#define NCL 3                 // classes 1..3 only (class 0 masked by reference)
#define NPRES (NB*NCL)
#define NPIX (NB*HH*WW)
#define NQUAD (NPIX/4)        // 131072 = 2^17
#define LOSS_BLOCKS ((NQUAD*NCL)/256)   // 1536

// Interleaved scratch: per pixel one uint = gp (low 16) | gn (high 16),
// for classes 1..3 only. 2*3*512*512*4 B = 6.3 MB (L2-resident).
__device__ __align__(16) unsigned int gpn_buf[(size_t)NB*NCL*HH*WW];
__device__ double g_acc;            // static-init 0; reset by last loss block
__device__ unsigned int g_count;    // static-init 0; reset by last loss block
__device__ int g_present[NPRES];    // static-init 0; reset by last loss block

// ---------------------------------------------------------------------------
// Kernel 1: row pass. One block per (n, r). 192 threads:
//   warps 0-2: forward scan for classes 1-3; warps 3-5: backward scan.
// Inline dtype probe: int64 labels (0..3) have all odd 32-bit words zero.
// g = min(fwd, bwd) distance-to-False, reference carry init 1e6 (clamped 60000).
// ---------------------------------------------------------------------------
__global__ void __launch_bounds__(192) row_pass(const int* __restrict__ tgt_words) {
    __shared__ unsigned char cls[WW];
    __shared__ unsigned short dfp[NCL][WW], dfn[NCL][WW];   // forward
    __shared__ unsigned short dbp[NCL][WW], dbn[NCL][WW];   // backward
    __shared__ __align__(16) ushort2 gstage[NCL][WW];       // combined (gp,gn)

    const int blk = blockIdx.x;          // n*H + r
    const int n = blk >> 9;
    const int r = blk & (HH - 1);
    const int tid = threadIdx.x;

    const size_t elem_base = ((size_t)n * HH + r) * WW;

    // Probe + load (threads 0..127 cover the row; int32 view always in-bounds)
    int4 v; int myodd = 0;
    if (tid < 128) {
        v = reinterpret_cast<const int4*>(tgt_words + elem_base)[tid];
        myodd = v.y | v.w;
    }
    if (__syncthreads_or(myodd)) {
        if (tid < 128) {
            cls[4 * tid + 0] = (unsigned char)v.x;
            cls[4 * tid + 1] = (unsigned char)v.y;
            cls[4 * tid + 2] = (unsigned char)v.z;
            cls[4 * tid + 3] = (unsigned char)v.w;
        }
    } else {
        if (tid < 128) {
            const longlong4 q = reinterpret_cast<const longlong4*>(
                tgt_words + 2 * elem_base)[tid];
            cls[4 * tid + 0] = (unsigned char)q.x;
            cls[4 * tid + 1] = (unsigned char)q.y;
            cls[4 * tid + 2] = (unsigned char)q.z;
            cls[4 * tid + 3] = (unsigned char)q.w;
        }
    }
    __syncthreads();

    const int warp = tid >> 5;
    const int lane = tid & 31;
    const int KBIG = 1 << 20;
    const int SINF = 1 << 26;
    const unsigned FULL = 0xffffffffu;

    if (warp < NCL) {
        // ---------------- forward (left-to-right), class = warp+1 ----------------
        const unsigned char cc = (unsigned char)(warp + 1);
        unsigned char cl[16];
        int dp = KBIG, dn = KBIG;
        bool found = false;
        #pragma unroll
        for (int i = 0; i < 16; i++) {
            cl[i] = cls[lane * 16 + i];
            bool m = (cl[i] == cc);
            found |= m;
            dp = m ? dp + 1 : 0;
            dn = m ? 0 : dn + 1;
        }
        int sp = (dp >= KBIG) ? SINF : dp;
        int sn = (dn >= KBIG) ? SINF : dn;
        #pragma unroll
        for (int off = 1; off < 32; off <<= 1) {
            int up_p = __shfl_up_sync(FULL, sp, off);
            int up_n = __shfl_up_sync(FULL, sn, off);
            if (lane >= off) {
                sp = min(up_p + 16 * off, sp);
                sn = min(up_n + 16 * off, sn);
            }
        }
        int ep = __shfl_up_sync(FULL, sp, 1);
        int en = __shfl_up_sync(FULL, sn, 1);
        int carp = (lane == 0) ? 1000000 : min(1000000 + 16 * lane, ep);
        int carn = (lane == 0) ? 1000000 : min(1000000 + 16 * lane, en);
        #pragma unroll
        for (int i = 0; i < 16; i++) {
            bool m = (cl[i] == cc);
            carp = m ? carp + 1 : 0;
            carn = m ? 0 : carn + 1;
            dfp[warp][lane * 16 + i] = (unsigned short)min(carp, 60000);
            dfn[warp][lane * 16 + i] = (unsigned short)min(carn, 60000);
        }
        if (__any_sync(FULL, found) && lane == 0)
            atomicOr(&g_present[n * NCL + warp], 1);
    } else {
        // ---------------- backward (right-to-left), class = warp-2 ----------------
        const int c = warp - NCL;            // 0..2 -> class c+1
        const unsigned char cc = (unsigned char)(c + 1);
        unsigned char cl[16];
        int dp = KBIG, dn = KBIG;
        #pragma unroll
        for (int i = 0; i < 16; i++) {
            cl[i] = cls[WW - 1 - lane * 16 - i];
            bool m = (cl[i] == cc);
            dp = m ? dp + 1 : 0;
            dn = m ? 0 : dn + 1;
        }
        int sp = (dp >= KBIG) ? SINF : dp;
        int sn = (dn >= KBIG) ? SINF : dn;
        #pragma unroll
        for (int off = 1; off < 32; off <<= 1) {
            int up_p = __shfl_up_sync(FULL, sp, off);
            int up_n = __shfl_up_sync(FULL, sn, off);
            if (lane >= off) {
                sp = min(up_p + 16 * off, sp);
                sn = min(up_n + 16 * off, sn);
            }
        }
        int ep = __shfl_up_sync(FULL, sp, 1);
        int en = __shfl_up_sync(FULL, sn, 1);
        int carp = (lane == 0) ? 1000000 : min(1000000 + 16 * lane, ep);
        int carn = (lane == 0) ? 1000000 : min(1000000 + 16 * lane, en);
        #pragma unroll
        for (int i = 0; i < 16; i++) {
            int x = WW - 1 - lane * 16 - i;
            bool m = (cl[i] == cc);
            carp = m ? carp + 1 : 0;
            carn = m ? 0 : carn + 1;
            dbp[c][x] = (unsigned short)min(carp, 60000);
            dbn[c][x] = (unsigned short)min(carn, 60000);
        }
    }
    __syncthreads();

    // ---------------- combine fwd/bwd, stage interleaved ----------------
    #pragma unroll
    for (int k = 0; k < 8; k++) {
        int i2 = k * 192 + tid;              // 0..1535
        int c2 = i2 >> 9;                    // class idx 0..2
        int x  = i2 & (WW - 1);
        unsigned short p = min(dfp[c2][x], dbp[c2][x]);
        unsigned short q = min(dfn[c2][x], dbn[c2][x]);
        gstage[c2][x] = make_ushort2(p, q);  // low=gp, high=gn
    }
    __syncthreads();

    // ---------------- coalesced uint4 write-out ----------------
    const uint4* s = reinterpret_cast<const uint4*>(&gstage[0][0]);
    uint4* dg = reinterpret_cast<uint4*>(gpn_buf);
    #pragma unroll
    for (int k = 0; k < 2; k++) {
        int i2 = k * 192 + tid;              // 0..383
        int c2 = i2 >> 7;                    // class idx 0..2
        int j  = i2 & 127;                   // uint4 within row
        size_t off = ((size_t)(n * NCL + c2) * HH + r) * (WW / 4) + j;
        dg[off] = s[i2];
    }
}

// ---------------------------------------------------------------------------
// Kernel 2: fused softmax + signed EDT + reduction + tail finalize.
// Thread = (class, quad): 4 horizontally adjacent pixels of ONE class.
//   idx top bits = class -> coalescing preserved within each population.
//   Per-thread state small (~40 regs) -> high occupancy; 5 independent uint4
//   probe loads in flight (center + d=1,2 window). Rare d>=3 serial tail.
// Absent classes skip all work (exact 0, matches reference zeroing).
// Clamped probe rows are dominated by earlier-visited true offsets.
// ---------------------------------------------------------------------------
__global__ void __launch_bounds__(256) loss_pass(const float* __restrict__ logits,
                                                 float* __restrict__ out) {
    const int idx = blockIdx.x * 256 + threadIdx.x;
    const int ci = idx >> 17;                 // class idx 0..2  (class ci+1)
    const int q = idx & (NQUAD - 1);
    const int x = (q & 127) * 4;
    const int r = (q >> 7) & (HH - 1);
    const int n = q >> 16;
    const int pix = r * WW + x;

    double local = 0.0;
    if (g_present[n * NCL + ci]) {            // uniform within population
        // ---- probes: center + d=1,2 window, 5 independent uint4 loads ----
        const unsigned int* col = gpn_buf + ((size_t)(n * NCL + ci) * HH) * WW + x;
        uint4 wc = *reinterpret_cast<const uint4*>(col + r * WW);
        uint4 u1 = *reinterpret_cast<const uint4*>(col + max(r - 1, 0) * WW);
        uint4 d1 = *reinterpret_cast<const uint4*>(col + min(r + 1, HH - 1) * WW);
        uint4 u2 = *reinterpret_cast<const uint4*>(col + max(r - 2, 0) * WW);
        uint4 d2 = *reinterpret_cast<const uint4*>(col + min(r + 2, HH - 1) * WW);

        // ---- softmax prob of class ci+1 for 4 pixels (overlaps with loads) ----
        float4 lv[NC];
        #pragma unroll
        for (int c = 0; c < NC; c++)
            lv[c] = *reinterpret_cast<const float4*>(
                logits + (size_t)(n * NC + c) * (HH * WW) + pix);
        float prob[4];
        #pragma unroll
        for (int j = 0; j < 4; j++) {
            float l0 = (&lv[0].x)[j], l1 = (&lv[1].x)[j];
            float l2 = (&lv[2].x)[j], l3 = (&lv[3].x)[j];
            float mx = fmaxf(fmaxf(l0, l1), fmaxf(l2, l3));
            float e0 = __expf(l0 - mx), e1 = __expf(l1 - mx);
            float e2 = __expf(l2 - mx), e3 = __expf(l3 - mx);
            float ec = (ci == 0) ? e1 : ((ci == 1) ? e2 : e3);
            prob[j] = ec / (e0 + e1 + e2 + e3);
        }

        // ---- min-plus ----
        unsigned int bp[4], bn[4], bmax = 0u;
        #pragma unroll
        for (int j = 0; j < 4; j++) {
            unsigned int w = (&wc.x)[j];
            unsigned int gp = w & 0xffffu, gn = w >> 16;
            bp[j] = gp * gp; bn[j] = gn * gn;
            unsigned int t;
            t = (&u1.x)[j] & 0xffffu; bp[j] = min(bp[j], t * t + 1u);
            t = (&u1.x)[j] >> 16;     bn[j] = min(bn[j], t * t + 1u);
            t = (&d1.x)[j] & 0xffffu; bp[j] = min(bp[j], t * t + 1u);
            t = (&d1.x)[j] >> 16;     bn[j] = min(bn[j], t * t + 1u);
            t = (&u2.x)[j] & 0xffffu; bp[j] = min(bp[j], t * t + 4u);
            t = (&u2.x)[j] >> 16;     bn[j] = min(bn[j], t * t + 4u);
            t = (&d2.x)[j] & 0xffffu; bp[j] = min(bp[j], t * t + 4u);
            t = (&d2.x)[j] >> 16;     bn[j] = min(bn[j], t * t + 4u);
            bmax = max(bmax, max(bp[j], bn[j]));
        }
        // rare serial tail, d >= 3
        #pragma unroll 1
        for (int d = 3; (unsigned int)(d * d) < bmax; ++d) {
            uint4 wu = *reinterpret_cast<const uint4*>(col + max(r - d, 0) * WW);
            uint4 wd = *reinterpret_cast<const uint4*>(col + min(r + d, HH - 1) * WW);
            unsigned int dd = (unsigned int)(d * d);
            bmax = 0u;
            #pragma unroll
            for (int j = 0; j < 4; j++) {
                unsigned int t;
                t = (&wu.x)[j] & 0xffffu; bp[j] = min(bp[j], t * t + dd);
                t = (&wu.x)[j] >> 16;     bn[j] = min(bn[j], t * t + dd);
                t = (&wd.x)[j] & 0xffffu; bp[j] = min(bp[j], t * t + dd);
                t = (&wd.x)[j] >> 16;     bn[j] = min(bn[j], t * t + dd);
                bmax = max(bmax, max(bp[j], bn[j]));
            }
        }

        float acc = 0.0f;
        #pragma unroll
        for (int j = 0; j < 4; j++)
            acc += prob[j] * (sqrtf((float)bn[j]) - sqrtf((float)bp[j]));
        local = (double)acc;
    }

    // ---- block reduction (double) + tail finalize ----
    __shared__ double warp_sums[8];
    __shared__ bool is_last;
    const unsigned FULL = 0xffffffffu;
    #pragma unroll
    for (int off = 16; off > 0; off >>= 1)
        local += __shfl_down_sync(FULL, local, off);
    const int lane = threadIdx.x & 31;
    const int wid = threadIdx.x >> 5;
    if (lane == 0) warp_sums[wid] = local;
    __syncthreads();
    if (wid == 0) {
        double v = (lane < 8) ? warp_sums[lane] : 0.0;
        #pragma unroll
        for (int off = 4; off > 0; off >>= 1)
            v += __shfl_down_sync(FULL, v, off);
        if (lane == 0) {
            atomicAdd(&g_acc, v);
            __threadfence();
            unsigned int t = atomicAdd(&g_count, 1u);
            is_last = (t == gridDim.x - 1);
        }
    }
    __syncthreads();
    // Last block finalizes and restores all device state (deterministic replay)
    if (is_last) {
        if (threadIdx.x == 0) {
            __threadfence();
            double total = g_acc;
            // mean over N*C*H*W = 2*4*512*512 = 2^21 elements
            out[0] = (float)(total * (1.0 / 2097152.0));
            g_acc = 0.0;
            g_count = 0u;
        }
        if (threadIdx.x < NPRES) g_present[threadIdx.x] = 0;
    }
}

extern "C" void kernel_launch(void* const* d_in, const int* in_sizes, int n_in,
                              void* d_out, int out_size) {
    const float* logits = (const float*)d_in[0];     // [2,4,512,512] fp32
    const int* tgt_words = (const int*)d_in[1];      // [2,512,512] int32 or int64
    float* out = (float*)d_out;

    row_pass<<<NB * HH, 192>>>(tgt_words);
    loss_pass<<<LOSS_BLOCKS, 256>>>(logits, out);
}

// round 15
// speedup vs baseline: 1.0094x; 1.0094x over previous
#include <cuda_runtime.h>
#include <stdint.h>

#define HH 512
#define WW 512
#define NB 2
#define NC 4
#define NCL 3                 // classes 1..3 only (class 0 masked by reference)
#define NPRES (NB*NCL)
#define NPIX (NB*HH*WW)
#define NQUAD (NPIX/4)        // 131072

// Interleaved scratch: per pixel one uint = gp (low 16) | gn (high 16),
// for classes 1..3 only. 2*3*512*512*4 B = 6.3 MB (L2-resident).
__device__ __align__(16) unsigned int gpn_buf[(size_t)NB*NCL*HH*WW];
__device__ double g_acc;            // static-init 0; reset by last loss block
__device__ unsigned int g_count;    // static-init 0; reset by last loss block
__device__ int g_present[NPRES];    // static-init 0; reset by last loss block

// ---------------------------------------------------------------------------
// Kernel 1: row pass. One block per (n, r). 192 threads:
//   warps 0-2: forward scan for classes 1-3; warps 3-5: backward scan.
// Inline dtype probe: int64 labels (0..3) have all odd 32-bit words zero.
// g = min(fwd, bwd) distance-to-False, reference carry init 1e6 (clamped 60000).
// ---------------------------------------------------------------------------
__global__ void __launch_bounds__(192) row_pass(const int* __restrict__ tgt_words) {
    __shared__ unsigned char cls[WW];
    __shared__ unsigned short dfp[NCL][WW], dfn[NCL][WW];   // forward
    __shared__ unsigned short dbp[NCL][WW], dbn[NCL][WW];   // backward
    __shared__ __align__(16) ushort2 gstage[NCL][WW];       // combined (gp,gn)

    const int blk = blockIdx.x;          // n*H + r
    const int n = blk >> 9;
    const int r = blk & (HH - 1);
    const int tid = threadIdx.x;

    const size_t elem_base = ((size_t)n * HH + r) * WW;

    // Probe + load (threads 0..127 cover the row; int32 view always in-bounds)
    int4 v; int myodd = 0;
    if (tid < 128) {
        v = reinterpret_cast<const int4*>(tgt_words + elem_base)[tid];
        myodd = v.y | v.w;
    }
    if (__syncthreads_or(myodd)) {
        if (tid < 128) {
            cls[4 * tid + 0] = (unsigned char)v.x;
            cls[4 * tid + 1] = (unsigned char)v.y;
            cls[4 * tid + 2] = (unsigned char)v.z;
            cls[4 * tid + 3] = (unsigned char)v.w;
        }
    } else {
        if (tid < 128) {
            const longlong4 q = reinterpret_cast<const longlong4*>(
                tgt_words + 2 * elem_base)[tid];
            cls[4 * tid + 0] = (unsigned char)q.x;
            cls[4 * tid + 1] = (unsigned char)q.y;
            cls[4 * tid + 2] = (unsigned char)q.z;
            cls[4 * tid + 3] = (unsigned char)q.w;
        }
    }
    __syncthreads();

    const int warp = tid >> 5;
    const int lane = tid & 31;
    const int KBIG = 1 << 20;
    const int SINF = 1 << 26;
    const unsigned FULL = 0xffffffffu;

    if (warp < NCL) {
        // ---------------- forward (left-to-right), class = warp+1 ----------------
        const unsigned char cc = (unsigned char)(warp + 1);
        unsigned char cl[16];
        int dp = KBIG, dn = KBIG;
        bool found = false;
        #pragma unroll
        for (int i = 0; i < 16; i++) {
            cl[i] = cls[lane * 16 + i];
            bool m = (cl[i] == cc);
            found |= m;
            dp = m ? dp + 1 : 0;
            dn = m ? 0 : dn + 1;
        }
        int sp = (dp >= KBIG) ? SINF : dp;
        int sn = (dn >= KBIG) ? SINF : dn;
        #pragma unroll
        for (int off = 1; off < 32; off <<= 1) {
            int up_p = __shfl_up_sync(FULL, sp, off);
            int up_n = __shfl_up_sync(FULL, sn, off);
            if (lane >= off) {
                sp = min(up_p + 16 * off, sp);
                sn = min(up_n + 16 * off, sn);
            }
        }
        int ep = __shfl_up_sync(FULL, sp, 1);
        int en = __shfl_up_sync(FULL, sn, 1);
        int carp = (lane == 0) ? 1000000 : min(1000000 + 16 * lane, ep);
        int carn = (lane == 0) ? 1000000 : min(1000000 + 16 * lane, en);
        #pragma unroll
        for (int i = 0; i < 16; i++) {
            bool m = (cl[i] == cc);
            carp = m ? carp + 1 : 0;
            carn = m ? 0 : carn + 1;
            dfp[warp][lane * 16 + i] = (unsigned short)min(carp, 60000);
            dfn[warp][lane * 16 + i] = (unsigned short)min(carn, 60000);
        }
        if (__any_sync(FULL, found) && lane == 0)
            atomicOr(&g_present[n * NCL + warp], 1);
    } else {
        // ---------------- backward (right-to-left), class = warp-2 ----------------
        const int c = warp - NCL;            // 0..2 -> class c+1
        const unsigned char cc = (unsigned char)(c + 1);
        unsigned char cl[16];
        int dp = KBIG, dn = KBIG;
        #pragma unroll
        for (int i = 0; i < 16; i++) {
            cl[i] = cls[WW - 1 - lane * 16 - i];
            bool m = (cl[i] == cc);
            dp = m ? dp + 1 : 0;
            dn = m ? 0 : dn + 1;
        }
        int sp = (dp >= KBIG) ? SINF : dp;
        int sn = (dn >= KBIG) ? SINF : dn;
        #pragma unroll
        for (int off = 1; off < 32; off <<= 1) {
            int up_p = __shfl_up_sync(FULL, sp, off);
            int up_n = __shfl_up_sync(FULL, sn, off);
            if (lane >= off) {
                sp = min(up_p + 16 * off, sp);
                sn = min(up_n + 16 * off, sn);
            }
        }
        int ep = __shfl_up_sync(FULL, sp, 1);
        int en = __shfl_up_sync(FULL, sn, 1);
        int carp = (lane == 0) ? 1000000 : min(1000000 + 16 * lane, ep);
        int carn = (lane == 0) ? 1000000 : min(1000000 + 16 * lane, en);
        #pragma unroll
        for (int i = 0; i < 16; i++) {
            int x = WW - 1 - lane * 16 - i;
            bool m = (cl[i] == cc);
            carp = m ? carp + 1 : 0;
            carn = m ? 0 : carn + 1;
            dbp[c][x] = (unsigned short)min(carp, 60000);
            dbn[c][x] = (unsigned short)min(carn, 60000);
        }
    }
    __syncthreads();

    // ---------------- combine fwd/bwd, stage interleaved ----------------
    #pragma unroll
    for (int k = 0; k < 8; k++) {
        int i2 = k * 192 + tid;              // 0..1535
        int c2 = i2 >> 9;                    // class idx 0..2
        int x  = i2 & (WW - 1);
        unsigned short p = min(dfp[c2][x], dbp[c2][x]);
        unsigned short q = min(dfn[c2][x], dbn[c2][x]);
        gstage[c2][x] = make_ushort2(p, q);  // low=gp, high=gn
    }
    __syncthreads();

    // ---------------- coalesced uint4 write-out ----------------
    const uint4* s = reinterpret_cast<const uint4*>(&gstage[0][0]);
    uint4* dg = reinterpret_cast<uint4*>(gpn_buf);
    #pragma unroll
    for (int k = 0; k < 2; k++) {
        int i2 = k * 192 + tid;              // 0..383
        int c2 = i2 >> 7;                    // class idx 0..2
        int j  = i2 & 127;                   // uint4 within row
        size_t off = ((size_t)(n * NCL + c2) * HH + r) * (WW / 4) + j;
        dg[off] = s[i2];
    }
}

// ---------------------------------------------------------------------------
// Kernel 2: fused softmax + signed EDT + reduction + tail finalize.
// 4 pixels/thread, 3 classes interleaved for cross-class MLP (15 probe loads
// issued BEFORE softmax so L2 latency overlaps exp math). 128-thread blocks
// (grid 1024) for fine-grained SM balance. Tail processes (d, d+1) pairs —
// 4 independent loads per serial round trip. Absent classes masked to 0 at
// the center (mins never rise, tail skipped, term exactly 0 = reference).
// Clamped probe rows are dominated by earlier-visited true offsets.
// ---------------------------------------------------------------------------
__global__ void __launch_bounds__(128) loss_pass(const float* __restrict__ logits,
                                                 float* __restrict__ out) {
    const int idx = blockIdx.x * 128 + threadIdx.x;   // quad index
    const int x = (idx & 127) * 4;
    const int r = (idx >> 7) & (HH - 1);
    const int n = idx >> 16;
    const int pix = r * WW + x;

    // ---- issue all probe loads first (15 independent uint4) ----
    const unsigned int* col[NCL];
    unsigned int pres[NCL];
    uint4 wc[NCL], u1[NCL], d1[NCL], u2[NCL], d2[NCL];
    const int ru1 = max(r - 1, 0) * WW, rd1 = min(r + 1, HH - 1) * WW;
    const int ru2 = max(r - 2, 0) * WW, rd2 = min(r + 2, HH - 1) * WW;
    #pragma unroll
    for (int ci = 0; ci < NCL; ci++) {
        pres[ci] = (unsigned int)g_present[n * NCL + ci];
        col[ci] = gpn_buf + ((size_t)(n * NCL + ci) * HH) * WW + x;
        wc[ci] = *reinterpret_cast<const uint4*>(col[ci] + r * WW);
        u1[ci] = *reinterpret_cast<const uint4*>(col[ci] + ru1);
        d1[ci] = *reinterpret_cast<const uint4*>(col[ci] + rd1);
        u2[ci] = *reinterpret_cast<const uint4*>(col[ci] + ru2);
        d2[ci] = *reinterpret_cast<const uint4*>(col[ci] + rd2);
    }

    // ---- softmax probs for classes 1..3, 4 pixels (overlaps probe latency) ----
    float prob[NCL][4];
    {
        float4 lv[NC];
        #pragma unroll
        for (int c = 0; c < NC; c++)
            lv[c] = *reinterpret_cast<const float4*>(
                logits + (size_t)(n * NC + c) * (HH * WW) + pix);
        #pragma unroll
        for (int j = 0; j < 4; j++) {
            float l0 = (&lv[0].x)[j], l1 = (&lv[1].x)[j];
            float l2 = (&lv[2].x)[j], l3 = (&lv[3].x)[j];
            float mx = fmaxf(fmaxf(l0, l1), fmaxf(l2, l3));
            float e0 = __expf(l0 - mx), e1 = __expf(l1 - mx);
            float e2 = __expf(l2 - mx), e3 = __expf(l3 - mx);
            float inv = 1.0f / (e0 + e1 + e2 + e3);
            prob[0][j] = e1 * inv;
            prob[1][j] = e2 * inv;
            prob[2][j] = e3 * inv;
        }
    }

    // ---- min-plus: center (masked) + d=1,2 window ----
    unsigned int bp[NCL][4], bn[NCL][4];
    #pragma unroll
    for (int ci = 0; ci < NCL; ci++) {
        #pragma unroll
        for (int j = 0; j < 4; j++) {
            unsigned int w = (&wc[ci].x)[j];
            unsigned int gp = w & 0xffffu, gn = w >> 16;
            bp[ci][j] = pres[ci] ? gp * gp : 0u;   // absent -> exact 0
            bn[ci][j] = pres[ci] ? gn * gn : 0u;
            unsigned int t;
            t = (&u1[ci].x)[j] & 0xffffu; bp[ci][j] = min(bp[ci][j], t * t + 1u);
            t = (&u1[ci].x)[j] >> 16;     bn[ci][j] = min(bn[ci][j], t * t + 1u);
            t = (&d1[ci].x)[j] & 0xffffu; bp[ci][j] = min(bp[ci][j], t * t + 1u);
            t = (&d1[ci].x)[j] >> 16;     bn[ci][j] = min(bn[ci][j], t * t + 1u);
            t = (&u2[ci].x)[j] & 0xffffu; bp[ci][j] = min(bp[ci][j], t * t + 4u);
            t = (&u2[ci].x)[j] >> 16;     bn[ci][j] = min(bn[ci][j], t * t + 4u);
            t = (&d2[ci].x)[j] & 0xffffu; bp[ci][j] = min(bp[ci][j], t * t + 4u);
            t = (&d2[ci].x)[j] >> 16;     bn[ci][j] = min(bn[ci][j], t * t + 4u);
        }
    }

    // ---- rare serial tails, per class, (d, d+1) pairs ----
    #pragma unroll
    for (int ci = 0; ci < NCL; ci++) {
        unsigned int bmax = 0u;
        #pragma unroll
        for (int j = 0; j < 4; j++) bmax = max(bmax, max(bp[ci][j], bn[ci][j]));
        #pragma unroll 1
        for (int d = 3; (unsigned int)(d * d) < bmax; d += 2) {
            const uint4 wu = *reinterpret_cast<const uint4*>(col[ci] + max(r - d, 0) * WW);
            const uint4 wd = *reinterpret_cast<const uint4*>(col[ci] + min(r + d, HH - 1) * WW);
            const uint4 xu = *reinterpret_cast<const uint4*>(col[ci] + max(r - d - 1, 0) * WW);
            const uint4 xd = *reinterpret_cast<const uint4*>(col[ci] + min(r + d + 1, HH - 1) * WW);
            unsigned int dd = (unsigned int)(d * d);
            unsigned int ee = (unsigned int)((d + 1) * (d + 1));
            bmax = 0u;
            #pragma unroll
            for (int j = 0; j < 4; j++) {
                unsigned int t;
                t = (&wu.x)[j] & 0xffffu; bp[ci][j] = min(bp[ci][j], t * t + dd);
                t = (&wu.x)[j] >> 16;     bn[ci][j] = min(bn[ci][j], t * t + dd);
                t = (&wd.x)[j] & 0xffffu; bp[ci][j] = min(bp[ci][j], t * t + dd);
                t = (&wd.x)[j] >> 16;     bn[ci][j] = min(bn[ci][j], t * t + dd);
                t = (&xu.x)[j] & 0xffffu; bp[ci][j] = min(bp[ci][j], t * t + ee);
                t = (&xu.x)[j] >> 16;     bn[ci][j] = min(bn[ci][j], t * t + ee);
                t = (&xd.x)[j] & 0xffffu; bp[ci][j] = min(bp[ci][j], t * t + ee);
                t = (&xd.x)[j] >> 16;     bn[ci][j] = min(bn[ci][j], t * t + ee);
                bmax = max(bmax, max(bp[ci][j], bn[ci][j]));
            }
        }
    }

    // ---- accumulate ----
    float acc = 0.0f;
    #pragma unroll
    for (int ci = 0; ci < NCL; ci++)
        #pragma unroll
        for (int j = 0; j < 4; j++)
            acc += prob[ci][j] * (sqrtf((float)bn[ci][j]) - sqrtf((float)bp[ci][j]));
    double local = (double)acc;

    // ---- block reduction (double) + tail finalize ----
    __shared__ double warp_sums[4];
    __shared__ bool is_last;
    const unsigned FULL = 0xffffffffu;
    #pragma unroll
    for (int off = 16; off > 0; off >>= 1)
        local += __shfl_down_sync(FULL, local, off);
    const int lane = threadIdx.x & 31;
    const int wid = threadIdx.x >> 5;
    if (lane == 0) warp_sums[wid] = local;
    __syncthreads();
    if (wid == 0) {
        double v = (lane < 4) ? warp_sums[lane] : 0.0;
        #pragma unroll
        for (int off = 2; off > 0; off >>= 1)
            v += __shfl_down_sync(FULL, v, off);
        if (lane == 0) {
            atomicAdd(&g_acc, v);
            __threadfence();
            unsigned int t = atomicAdd(&g_count, 1u);
            is_last = (t == gridDim.x - 1);
        }
    }
    __syncthreads();
    // Last block finalizes and restores all device state (deterministic replay)
    if (is_last) {
        if (threadIdx.x == 0) {
            __threadfence();
            double total = g_acc;
            // mean over N*C*H*W = 2*4*512*512 = 2^21 elements
            out[0] = (float)(total * (1.0 / 2097152.0));
            g_acc = 0.0;
            g_count = 0u;
        }
        if (threadIdx.x < NPRES) g_present[threadIdx.x] = 0;
    }
}

extern "C" void kernel_launch(void* const* d_in, const int* in_sizes, int n_in,
                              void* d_out, int out_size) {
    const float* logits = (const float*)d_in[0];     // [2,4,512,512] fp32
    const int* tgt_words = (const int*)d_in[1];      // [2,512,512] int32 or int64
    float* out = (float*)d_out;

    row_pass<<<NB * HH, 192>>>(tgt_words);
    loss_pass<<<NQUAD / 128, 128>>>(logits, out);
}

// round 16
// speedup vs baseline: 1.0808x; 1.0707x over previous
#include <cuda_runtime.h>
#include <stdint.h>

#define HH 512
#define WW 512
#define NB 2
#define NC 4
#define NCL 3                 // classes 1..3 only (class 0 masked by reference)
#define NPRES (NB*NCL)
#define NPIX (NB*HH*WW)

// Interleaved scratch: per pixel one uint = gp (low 16) | gn (high 16),
// for classes 1..3 only. 2*3*512*512*4 B = 6.3 MB (L2-resident).
__device__ __align__(16) unsigned int gpn_buf[(size_t)NB*NCL*HH*WW];
__device__ double g_acc;            // static-init 0; reset by last loss block
__device__ unsigned int g_count;    // static-init 0; reset by last loss block
__device__ int g_present[NPRES];    // static-init 0; reset by last loss block

// ---------------------------------------------------------------------------
// Kernel 1: row pass. One block per (n, r). 192 threads:
//   warps 0-2: forward scan for classes 1-3; warps 3-5: backward scan.
// Inline dtype probe: int64 labels (0..3) have all odd 32-bit words zero.
// g = min(fwd, bwd) distance-to-False, reference carry init 1e6 (clamped 60000).
// Combine uses packed-u16 min (__vminu2) + __byte_perm interleave, writing the
// final uint4 directly to gmem (no staging pass).
// ---------------------------------------------------------------------------
__global__ void __launch_bounds__(192) row_pass(const int* __restrict__ tgt_words) {
    __shared__ unsigned char cls[WW];
    __shared__ __align__(8) unsigned short dfp[NCL][WW], dfn[NCL][WW];   // forward
    __shared__ __align__(8) unsigned short dbp[NCL][WW], dbn[NCL][WW];   // backward

    const int blk = blockIdx.x;          // n*H + r
    const int n = blk >> 9;
    const int r = blk & (HH - 1);
    const int tid = threadIdx.x;

    const size_t elem_base = ((size_t)n * HH + r) * WW;

    // Probe + load (threads 0..127 cover the row; int32 view always in-bounds)
    int4 v; int myodd = 0;
    if (tid < 128) {
        v = reinterpret_cast<const int4*>(tgt_words + elem_base)[tid];
        myodd = v.y | v.w;
    }
    if (__syncthreads_or(myodd)) {
        if (tid < 128) {
            cls[4 * tid + 0] = (unsigned char)v.x;
            cls[4 * tid + 1] = (unsigned char)v.y;
            cls[4 * tid + 2] = (unsigned char)v.z;
            cls[4 * tid + 3] = (unsigned char)v.w;
        }
    } else {
        if (tid < 128) {
            const longlong4 q = reinterpret_cast<const longlong4*>(
                tgt_words + 2 * elem_base)[tid];
            cls[4 * tid + 0] = (unsigned char)q.x;
            cls[4 * tid + 1] = (unsigned char)q.y;
            cls[4 * tid + 2] = (unsigned char)q.z;
            cls[4 * tid + 3] = (unsigned char)q.w;
        }
    }
    __syncthreads();

    const int warp = tid >> 5;
    const int lane = tid & 31;
    const int KBIG = 1 << 20;
    const int SINF = 1 << 26;
    const unsigned FULL = 0xffffffffu;

    if (warp < NCL) {
        // ---------------- forward (left-to-right), class = warp+1 ----------------
        const unsigned char cc = (unsigned char)(warp + 1);
        unsigned char cl[16];
        int dp = KBIG, dn = KBIG;
        bool found = false;
        #pragma unroll
        for (int i = 0; i < 16; i++) {
            cl[i] = cls[lane * 16 + i];
            bool m = (cl[i] == cc);
            found |= m;
            dp = m ? dp + 1 : 0;
            dn = m ? 0 : dn + 1;
        }
        int sp = (dp >= KBIG) ? SINF : dp;
        int sn = (dn >= KBIG) ? SINF : dn;
        #pragma unroll
        for (int off = 1; off < 32; off <<= 1) {
            int up_p = __shfl_up_sync(FULL, sp, off);
            int up_n = __shfl_up_sync(FULL, sn, off);
            if (lane >= off) {
                sp = min(up_p + 16 * off, sp);
                sn = min(up_n + 16 * off, sn);
            }
        }
        int ep = __shfl_up_sync(FULL, sp, 1);
        int en = __shfl_up_sync(FULL, sn, 1);
        int carp = (lane == 0) ? 1000000 : min(1000000 + 16 * lane, ep);
        int carn = (lane == 0) ? 1000000 : min(1000000 + 16 * lane, en);
        #pragma unroll
        for (int i = 0; i < 16; i++) {
            bool m = (cl[i] == cc);
            carp = m ? carp + 1 : 0;
            carn = m ? 0 : carn + 1;
            dfp[warp][lane * 16 + i] = (unsigned short)min(carp, 60000);
            dfn[warp][lane * 16 + i] = (unsigned short)min(carn, 60000);
        }
        if (__any_sync(FULL, found) && lane == 0)
            atomicOr(&g_present[n * NCL + warp], 1);
    } else {
        // ---------------- backward (right-to-left), class = warp-2 ----------------
        const int c = warp - NCL;            // 0..2 -> class c+1
        const unsigned char cc = (unsigned char)(c + 1);
        unsigned char cl[16];
        int dp = KBIG, dn = KBIG;
        #pragma unroll
        for (int i = 0; i < 16; i++) {
            cl[i] = cls[WW - 1 - lane * 16 - i];
            bool m = (cl[i] == cc);
            dp = m ? dp + 1 : 0;
            dn = m ? 0 : dn + 1;
        }
        int sp = (dp >= KBIG) ? SINF : dp;
        int sn = (dn >= KBIG) ? SINF : dn;
        #pragma unroll
        for (int off = 1; off < 32; off <<= 1) {
            int up_p = __shfl_up_sync(FULL, sp, off);
            int up_n = __shfl_up_sync(FULL, sn, off);
            if (lane >= off) {
                sp = min(up_p + 16 * off, sp);
                sn = min(up_n + 16 * off, sn);
            }
        }
        int ep = __shfl_up_sync(FULL, sp, 1);
        int en = __shfl_up_sync(FULL, sn, 1);
        int carp = (lane == 0) ? 1000000 : min(1000000 + 16 * lane, ep);
        int carn = (lane == 0) ? 1000000 : min(1000000 + 16 * lane, en);
        #pragma unroll
        for (int i = 0; i < 16; i++) {
            int x = WW - 1 - lane * 16 - i;
            bool m = (cl[i] == cc);
            carp = m ? carp + 1 : 0;
            carn = m ? 0 : carn + 1;
            dbp[c][x] = (unsigned short)min(carp, 60000);
            dbn[c][x] = (unsigned short)min(carn, 60000);
        }
    }
    __syncthreads();

    // ------- combine fwd/bwd (packed u16 min) + direct uint4 write-out -------
    // 384 uint4 groups (3 classes x 128), 192 threads -> 2 each.
    uint4* dg = reinterpret_cast<uint4*>(gpn_buf);
    #pragma unroll
    for (int k = 0; k < 2; k++) {
        int i2 = k * 192 + tid;              // 0..383
        int c2 = i2 >> 7;                    // class idx 0..2
        int j  = i2 & 127;                   // uint4 within row (4 pixels)
        int x  = j * 4;
        uint2 fp = *reinterpret_cast<const uint2*>(&dfp[c2][x]);
        uint2 bp = *reinterpret_cast<const uint2*>(&dbp[c2][x]);
        uint2 fn = *reinterpret_cast<const uint2*>(&dfn[c2][x]);
        uint2 bn = *reinterpret_cast<const uint2*>(&dbn[c2][x]);
        unsigned int p2a = __vminu2(fp.x, bp.x);   // pixels x, x+1 (gp)
        unsigned int p2b = __vminu2(fp.y, bp.y);   // pixels x+2, x+3
        unsigned int q2a = __vminu2(fn.x, bn.x);   // (gn)
        unsigned int q2b = __vminu2(fn.y, bn.y);
        uint4 o;
        o.x = __byte_perm(p2a, q2a, 0x5410);       // gp|gn<<16 pixel x
        o.y = __byte_perm(p2a, q2a, 0x7632);       // pixel x+1
        o.z = __byte_perm(p2b, q2b, 0x5410);       // pixel x+2
        o.w = __byte_perm(p2b, q2b, 0x7632);       // pixel x+3
        dg[((size_t)(n * NCL + c2) * HH + r) * (WW / 4) + j] = o;
    }
}

// ---------------------------------------------------------------------------
// Kernel 2: fused softmax + signed EDT + reduction + tail finalize.
// 4 pixels/thread, classes unrolled (round-9 balance: issue-per-class).
//   phase 1: 3 center uint4 loads; phase 2: per class 6 window loads d=1..3;
//   phase 3: rare per-class serial tails from d=4, (d,d+1) pairs.
// Absent classes masked to 0 at the center (mins never rise, tail skipped,
// term exactly 0 = reference). Clamped probe rows dominated by earlier d.
// ---------------------------------------------------------------------------
__global__ void __launch_bounds__(256) loss_pass(const float* __restrict__ logits,
                                                 float* __restrict__ out) {
    const int idx = blockIdx.x * 256 + threadIdx.x;   // quad index
    const int x = (idx & 127) * 4;
    const int r = (idx >> 7) & (HH - 1);
    const int n = idx >> 16;
    const int pix = r * WW + x;

    // ---- softmax probs for classes 1..3, 4 pixels ----
    float4 lv[NC];
    #pragma unroll
    for (int c = 0; c < NC; c++)
        lv[c] = *reinterpret_cast<const float4*>(
            logits + (size_t)(n * NC + c) * (HH * WW) + pix);
    float prob[NCL][4];
    #pragma unroll
    for (int j = 0; j < 4; j++) {
        float l0 = (&lv[0].x)[j], l1 = (&lv[1].x)[j];
        float l2 = (&lv[2].x)[j], l3 = (&lv[3].x)[j];
        float mx = fmaxf(fmaxf(l0, l1), fmaxf(l2, l3));
        float e0 = __expf(l0 - mx), e1 = __expf(l1 - mx);
        float e2 = __expf(l2 - mx), e3 = __expf(l3 - mx);
        float inv = 1.0f / (e0 + e1 + e2 + e3);
        prob[0][j] = e1 * inv;
        prob[1][j] = e2 * inv;
        prob[2][j] = e3 * inv;
    }

    // ---- phase 1: presence + center loads (3 independent) ----
    const unsigned int* col[NCL];
    unsigned int pres[NCL];
    uint4 wc[NCL];
    #pragma unroll
    for (int ci = 0; ci < NCL; ci++) {
        pres[ci] = (unsigned int)g_present[n * NCL + ci];
        col[ci] = gpn_buf + ((size_t)(n * NCL + ci) * HH) * WW + x;
        wc[ci] = *reinterpret_cast<const uint4*>(col[ci] + r * WW);
    }
    unsigned int bp[NCL][4], bn[NCL][4];
    #pragma unroll
    for (int ci = 0; ci < NCL; ci++) {
        #pragma unroll
        for (int j = 0; j < 4; j++) {
            unsigned int w = (&wc[ci].x)[j];
            unsigned int gp = w & 0xffffu, gn = w >> 16;
            bp[ci][j] = pres[ci] ? gp * gp : 0u;   // masked center: absent -> 0
            bn[ci][j] = pres[ci] ? gn * gn : 0u;
        }
    }

    // ---- phase 2: window d=1..3, per class (loads consumed immediately) ----
    const int ru1 = max(r - 1, 0) * WW, rd1 = min(r + 1, HH - 1) * WW;
    const int ru2 = max(r - 2, 0) * WW, rd2 = min(r + 2, HH - 1) * WW;
    const int ru3 = max(r - 3, 0) * WW, rd3 = min(r + 3, HH - 1) * WW;
    #pragma unroll
    for (int ci = 0; ci < NCL; ci++) {
        uint4 u1 = *reinterpret_cast<const uint4*>(col[ci] + ru1);
        uint4 d1 = *reinterpret_cast<const uint4*>(col[ci] + rd1);
        uint4 u2 = *reinterpret_cast<const uint4*>(col[ci] + ru2);
        uint4 d2 = *reinterpret_cast<const uint4*>(col[ci] + rd2);
        uint4 u3 = *reinterpret_cast<const uint4*>(col[ci] + ru3);
        uint4 d3 = *reinterpret_cast<const uint4*>(col[ci] + rd3);
        #pragma unroll
        for (int j = 0; j < 4; j++) {
            unsigned int t;
            t = (&u1.x)[j] & 0xffffu; bp[ci][j] = min(bp[ci][j], t * t + 1u);
            t = (&u1.x)[j] >> 16;     bn[ci][j] = min(bn[ci][j], t * t + 1u);
            t = (&d1.x)[j] & 0xffffu; bp[ci][j] = min(bp[ci][j], t * t + 1u);
            t = (&d1.x)[j] >> 16;     bn[ci][j] = min(bn[ci][j], t * t + 1u);
            t = (&u2.x)[j] & 0xffffu; bp[ci][j] = min(bp[ci][j], t * t + 4u);
            t = (&u2.x)[j] >> 16;     bn[ci][j] = min(bn[ci][j], t * t + 4u);
            t = (&d2.x)[j] & 0xffffu; bp[ci][j] = min(bp[ci][j], t * t + 4u);
            t = (&d2.x)[j] >> 16;     bn[ci][j] = min(bn[ci][j], t * t + 4u);
            t = (&u3.x)[j] & 0xffffu; bp[ci][j] = min(bp[ci][j], t * t + 9u);
            t = (&u3.x)[j] >> 16;     bn[ci][j] = min(bn[ci][j], t * t + 9u);
            t = (&d3.x)[j] & 0xffffu; bp[ci][j] = min(bp[ci][j], t * t + 9u);
            t = (&d3.x)[j] >> 16;     bn[ci][j] = min(bn[ci][j], t * t + 9u);
        }
    }

    // ---- phase 3: rare serial tails from d=4, (d, d+1) pairs ----
    #pragma unroll
    for (int ci = 0; ci < NCL; ci++) {
        unsigned int bmax = 0u;
        #pragma unroll
        for (int j = 0; j < 4; j++) bmax = max(bmax, max(bp[ci][j], bn[ci][j]));
        #pragma unroll 1
        for (int d = 4; (unsigned int)(d * d) < bmax; d += 2) {
            const uint4 wu = *reinterpret_cast<const uint4*>(col[ci] + max(r - d, 0) * WW);
            const uint4 wd = *reinterpret_cast<const uint4*>(col[ci] + min(r + d, HH - 1) * WW);
            const uint4 xu = *reinterpret_cast<const uint4*>(col[ci] + max(r - d - 1, 0) * WW);
            const uint4 xd = *reinterpret_cast<const uint4*>(col[ci] + min(r + d + 1, HH - 1) * WW);
            unsigned int dd = (unsigned int)(d * d);
            unsigned int ee = (unsigned int)((d + 1) * (d + 1));
            bmax = 0u;
            #pragma unroll
            for (int j = 0; j < 4; j++) {
                unsigned int t;
                t = (&wu.x)[j] & 0xffffu; bp[ci][j] = min(bp[ci][j], t * t + dd);
                t = (&wu.x)[j] >> 16;     bn[ci][j] = min(bn[ci][j], t * t + dd);
                t = (&wd.x)[j] & 0xffffu; bp[ci][j] = min(bp[ci][j], t * t + dd);
                t = (&wd.x)[j] >> 16;     bn[ci][j] = min(bn[ci][j], t * t + dd);
                t = (&xu.x)[j] & 0xffffu; bp[ci][j] = min(bp[ci][j], t * t + ee);
                t = (&xu.x)[j] >> 16;     bn[ci][j] = min(bn[ci][j], t * t + ee);
                t = (&xd.x)[j] & 0xffffu; bp[ci][j] = min(bp[ci][j], t * t + ee);
                t = (&xd.x)[j] >> 16;     bn[ci][j] = min(bn[ci][j], t * t + ee);
                bmax = max(bmax, max(bp[ci][j], bn[ci][j]));
            }
        }
    }

    // ---- accumulate ----
    float acc = 0.0f;
    #pragma unroll
    for (int ci = 0; ci < NCL; ci++)
        #pragma unroll
        for (int j = 0; j < 4; j++)
            acc += prob[ci][j] * (sqrtf((float)bn[ci][j]) - sqrtf((float)bp[ci][j]));
    double local = (double)acc;

    // ---- block reduction (double) + tail finalize ----
    __shared__ double warp_sums[8];
    __shared__ bool is_last;
    const unsigned FULL = 0xffffffffu;
    #pragma unroll
    for (int off = 16; off > 0; off >>= 1)
        local += __shfl_down_sync(FULL, local, off);
    const int lane = threadIdx.x & 31;
    const int wid = threadIdx.x >> 5;
    if (lane == 0) warp_sums[wid] = local;
    __syncthreads();
    if (wid == 0) {
        double v = (lane < 8) ? warp_sums[lane] : 0.0;
        #pragma unroll
        for (int off = 4; off > 0; off >>= 1)
            v += __shfl_down_sync(FULL, v, off);
        if (lane == 0) {
            atomicAdd(&g_acc, v);
            __threadfence();
            unsigned int t = atomicAdd(&g_count, 1u);
            is_last = (t == gridDim.x - 1);
        }
    }
    __syncthreads();
    // Last block finalizes and restores all device state (deterministic replay)
    if (is_last) {
        if (threadIdx.x == 0) {
            __threadfence();
            double total = g_acc;
            // mean over N*C*H*W = 2*4*512*512 = 2^21 elements
            out[0] = (float)(total * (1.0 / 2097152.0));
            g_acc = 0.0;
            g_count = 0u;
        }
        if (threadIdx.x < NPRES) g_present[threadIdx.x] = 0;
    }
}

extern "C" void kernel_launch(void* const* d_in, const int* in_sizes, int n_in,
                              void* d_out, int out_size) {
    const float* logits = (const float*)d_in[0];     // [2,4,512,512] fp32
    const int* tgt_words = (const int*)d_in[1];      // [2,512,512] int32 or int64
    float* out = (float*)d_out;

    row_pass<<<NB * HH, 192>>>(tgt_words);
    loss_pass<<<NPIX / 1024, 256>>>(logits, out);
}

// round 17
// speedup vs baseline: 1.3333x; 1.2336x over previous
#include <cuda_runtime.h>
#include <stdint.h>

#define HH 512
#define WW 512
#define NB 2
#define NC 4
#define NCL 3                 // classes 1..3 only (class 0 masked by reference)
#define NPRES (NB*NCL)
#define NPIX (NB*HH*WW)

// Interleaved scratch: per pixel one uint = gp (low 16) | gn (high 16),
// for classes 1..3 only. 2*3*512*512*4 B = 6.3 MB (L2-resident).
__device__ __align__(16) unsigned int gpn_buf[(size_t)NB*NCL*HH*WW];
__device__ double g_acc;            // static-init 0; reset by last loss block
__device__ unsigned int g_count;    // static-init 0; reset by last loss block
__device__ int g_present[NPRES];    // static-init 0; reset by last loss block

// ---------------------------------------------------------------------------
// Kernel 1: row pass. One block per (n, r). 192 threads:
//   warps 0-2: forward scan for classes 1-3; warps 3-5: backward scan.
// Inline dtype probe: int64 labels (0..3) have all odd 32-bit words zero.
// g = min(fwd, bwd) distance-to-False, reference carry init 1e6 (clamped 60000).
// Combine uses packed-u16 min (__vminu2) + __byte_perm interleave, writing the
// final uint4 directly to gmem (no staging pass).
// ---------------------------------------------------------------------------
__global__ void __launch_bounds__(192) row_pass(const int* __restrict__ tgt_words) {
    __shared__ unsigned char cls[WW];
    __shared__ __align__(8) unsigned short dfp[NCL][WW], dfn[NCL][WW];   // forward
    __shared__ __align__(8) unsigned short dbp[NCL][WW], dbn[NCL][WW];   // backward

    const int blk = blockIdx.x;          // n*H + r
    const int n = blk >> 9;
    const int r = blk & (HH - 1);
    const int tid = threadIdx.x;

    const size_t elem_base = ((size_t)n * HH + r) * WW;

    // Probe + load (threads 0..127 cover the row; int32 view always in-bounds)
    int4 v; int myodd = 0;
    if (tid < 128) {
        v = reinterpret_cast<const int4*>(tgt_words + elem_base)[tid];
        myodd = v.y | v.w;
    }
    if (__syncthreads_or(myodd)) {
        if (tid < 128) {
            cls[4 * tid + 0] = (unsigned char)v.x;
            cls[4 * tid + 1] = (unsigned char)v.y;
            cls[4 * tid + 2] = (unsigned char)v.z;
            cls[4 * tid + 3] = (unsigned char)v.w;
        }
    } else {
        if (tid < 128) {
            const longlong4 q = reinterpret_cast<const longlong4*>(
                tgt_words + 2 * elem_base)[tid];
            cls[4 * tid + 0] = (unsigned char)q.x;
            cls[4 * tid + 1] = (unsigned char)q.y;
            cls[4 * tid + 2] = (unsigned char)q.z;
            cls[4 * tid + 3] = (unsigned char)q.w;
        }
    }
    __syncthreads();

    const int warp = tid >> 5;
    const int lane = tid & 31;
    const int KBIG = 1 << 20;
    const int SINF = 1 << 26;
    const unsigned FULL = 0xffffffffu;

    if (warp < NCL) {
        // ---------------- forward (left-to-right), class = warp+1 ----------------
        const unsigned char cc = (unsigned char)(warp + 1);
        unsigned char cl[16];
        int dp = KBIG, dn = KBIG;
        bool found = false;
        #pragma unroll
        for (int i = 0; i < 16; i++) {
            cl[i] = cls[lane * 16 + i];
            bool m = (cl[i] == cc);
            found |= m;
            dp = m ? dp + 1 : 0;
            dn = m ? 0 : dn + 1;
        }
        int sp = (dp >= KBIG) ? SINF : dp;
        int sn = (dn >= KBIG) ? SINF : dn;
        #pragma unroll
        for (int off = 1; off < 32; off <<= 1) {
            int up_p = __shfl_up_sync(FULL, sp, off);
            int up_n = __shfl_up_sync(FULL, sn, off);
            if (lane >= off) {
                sp = min(up_p + 16 * off, sp);
                sn = min(up_n + 16 * off, sn);
            }
        }
        int ep = __shfl_up_sync(FULL, sp, 1);
        int en = __shfl_up_sync(FULL, sn, 1);
        int carp = (lane == 0) ? 1000000 : min(1000000 + 16 * lane, ep);
        int carn = (lane == 0) ? 1000000 : min(1000000 + 16 * lane, en);
        #pragma unroll
        for (int i = 0; i < 16; i++) {
            bool m = (cl[i] == cc);
            carp = m ? carp + 1 : 0;
            carn = m ? 0 : carn + 1;
            dfp[warp][lane * 16 + i] = (unsigned short)min(carp, 60000);
            dfn[warp][lane * 16 + i] = (unsigned short)min(carn, 60000);
        }
        if (__any_sync(FULL, found) && lane == 0)
            atomicOr(&g_present[n * NCL + warp], 1);
    } else {
        // ---------------- backward (right-to-left), class = warp-2 ----------------
        const int c = warp - NCL;            // 0..2 -> class c+1
        const unsigned char cc = (unsigned char)(c + 1);
        unsigned char cl[16];
        int dp = KBIG, dn = KBIG;
        #pragma unroll
        for (int i = 0; i < 16; i++) {
            cl[i] = cls[WW - 1 - lane * 16 - i];
            bool m = (cl[i] == cc);
            dp = m ? dp + 1 : 0;
            dn = m ? 0 : dn + 1;
        }
        int sp = (dp >= KBIG) ? SINF : dp;
        int sn = (dn >= KBIG) ? SINF : dn;
        #pragma unroll
        for (int off = 1; off < 32; off <<= 1) {
            int up_p = __shfl_up_sync(FULL, sp, off);
            int up_n = __shfl_up_sync(FULL, sn, off);
            if (lane >= off) {
                sp = min(up_p + 16 * off, sp);
                sn = min(up_n + 16 * off, sn);
            }
        }
        int ep = __shfl_up_sync(FULL, sp, 1);
        int en = __shfl_up_sync(FULL, sn, 1);
        int carp = (lane == 0) ? 1000000 : min(1000000 + 16 * lane, ep);
        int carn = (lane == 0) ? 1000000 : min(1000000 + 16 * lane, en);
        #pragma unroll
        for (int i = 0; i < 16; i++) {
            int x = WW - 1 - lane * 16 - i;
            bool m = (cl[i] == cc);
            carp = m ? carp + 1 : 0;
            carn = m ? 0 : carn + 1;
            dbp[c][x] = (unsigned short)min(carp, 60000);
            dbn[c][x] = (unsigned short)min(carn, 60000);
        }
    }
    __syncthreads();

    // ------- combine fwd/bwd (packed u16 min) + direct uint4 write-out -------
    // 384 uint4 groups (3 classes x 128), 192 threads -> 2 each.
    uint4* dg = reinterpret_cast<uint4*>(gpn_buf);
    #pragma unroll
    for (int k = 0; k < 2; k++) {
        int i2 = k * 192 + tid;              // 0..383
        int c2 = i2 >> 7;                    // class idx 0..2
        int j  = i2 & 127;                   // uint4 within row (4 pixels)
        int x  = j * 4;
        uint2 fp = *reinterpret_cast<const uint2*>(&dfp[c2][x]);
        uint2 bp = *reinterpret_cast<const uint2*>(&dbp[c2][x]);
        uint2 fn = *reinterpret_cast<const uint2*>(&dfn[c2][x]);
        uint2 bn = *reinterpret_cast<const uint2*>(&dbn[c2][x]);
        unsigned int p2a = __vminu2(fp.x, bp.x);   // pixels x, x+1 (gp)
        unsigned int p2b = __vminu2(fp.y, bp.y);   // pixels x+2, x+3
        unsigned int q2a = __vminu2(fn.x, bn.x);   // (gn)
        unsigned int q2b = __vminu2(fn.y, bn.y);
        uint4 o;
        o.x = __byte_perm(p2a, q2a, 0x5410);       // gp|gn<<16 pixel x
        o.y = __byte_perm(p2a, q2a, 0x7632);       // pixel x+1
        o.z = __byte_perm(p2b, q2b, 0x5410);       // pixel x+2
        o.w = __byte_perm(p2b, q2b, 0x7632);       // pixel x+3
        dg[((size_t)(n * NCL + c2) * HH + r) * (WW / 4) + j] = o;
    }
}

// ---------------------------------------------------------------------------
// Kernel 2: fused softmax + signed EDT + reduction + tail finalize.
// Launched with PDL (programmatic stream serialization): the softmax prologue
// (independent of row_pass output) runs while row_pass drains; the
// cudaGridDependencySynchronize() below orders all gpn_buf / g_present reads
// after row_pass completion.
// 4 pixels/thread, classes fully unrolled for cross-class MLP (round-9 form):
//   phase 1: 3 center uint4 loads; phase 2: 12 window uint4 loads (d=1,2);
//   phase 3: rare per-class serial tails from d=3. Absent classes masked to 0
//   at the center (mins never rise, tail skipped, term exactly 0 = reference).
// Clamped probe rows are dominated by earlier-visited true offsets.
// ---------------------------------------------------------------------------
__global__ void __launch_bounds__(256) loss_pass(const float* __restrict__ logits,
                                                 float* __restrict__ out) {
    const int idx = blockIdx.x * 256 + threadIdx.x;   // quad index
    const int x = (idx & 127) * 4;
    const int r = (idx >> 7) & (HH - 1);
    const int n = idx >> 16;
    const int pix = r * WW + x;

    // ---- softmax probs for classes 1..3, 4 pixels (pre-dependency work) ----
    float4 lv[NC];
    #pragma unroll
    for (int c = 0; c < NC; c++)
        lv[c] = *reinterpret_cast<const float4*>(
            logits + (size_t)(n * NC + c) * (HH * WW) + pix);
    float prob[NCL][4];
    #pragma unroll
    for (int j = 0; j < 4; j++) {
        float l0 = (&lv[0].x)[j], l1 = (&lv[1].x)[j];
        float l2 = (&lv[2].x)[j], l3 = (&lv[3].x)[j];
        float mx = fmaxf(fmaxf(l0, l1), fmaxf(l2, l3));
        float e0 = __expf(l0 - mx), e1 = __expf(l1 - mx);
        float e2 = __expf(l2 - mx), e3 = __expf(l3 - mx);
        float inv = 1.0f / (e0 + e1 + e2 + e3);
        prob[0][j] = e1 * inv;
        prob[1][j] = e2 * inv;
        prob[2][j] = e3 * inv;
    }

    // ---- wait for row_pass results to be visible ----
    cudaGridDependencySynchronize();

    // ---- phase 1: presence + center loads (3 independent) ----
    const unsigned int* col[NCL];
    unsigned int pres[NCL];
    uint4 wc[NCL];
    #pragma unroll
    for (int ci = 0; ci < NCL; ci++) {
        pres[ci] = (unsigned int)g_present[n * NCL + ci];
        col[ci] = gpn_buf + ((size_t)(n * NCL + ci) * HH) * WW + x;
        wc[ci] = *reinterpret_cast<const uint4*>(col[ci] + r * WW);
    }
    unsigned int bp[NCL][4], bn[NCL][4];
    #pragma unroll
    for (int ci = 0; ci < NCL; ci++) {
        #pragma unroll
        for (int j = 0; j < 4; j++) {
            unsigned int w = (&wc[ci].x)[j];
            unsigned int gp = w & 0xffffu, gn = w >> 16;
            bp[ci][j] = pres[ci] ? gp * gp : 0u;   // masked center: absent -> 0
            bn[ci][j] = pres[ci] ? gn * gn : 0u;
        }
    }

    // ---- phase 2: window d=1,2 — 12 independent loads ----
    const int ru1 = max(r - 1, 0) * WW, rd1 = min(r + 1, HH - 1) * WW;
    const int ru2 = max(r - 2, 0) * WW, rd2 = min(r + 2, HH - 1) * WW;
    #pragma unroll
    for (int ci = 0; ci < NCL; ci++) {
        uint4 u1 = *reinterpret_cast<const uint4*>(col[ci] + ru1);
        uint4 d1 = *reinterpret_cast<const uint4*>(col[ci] + rd1);
        uint4 u2 = *reinterpret_cast<const uint4*>(col[ci] + ru2);
        uint4 d2 = *reinterpret_cast<const uint4*>(col[ci] + rd2);
        #pragma unroll
        for (int j = 0; j < 4; j++) {
            unsigned int t;
            t = (&u1.x)[j] & 0xffffu; bp[ci][j] = min(bp[ci][j], t * t + 1u);
            t = (&u1.x)[j] >> 16;     bn[ci][j] = min(bn[ci][j], t * t + 1u);
            t = (&d1.x)[j] & 0xffffu; bp[ci][j] = min(bp[ci][j], t * t + 1u);
            t = (&d1.x)[j] >> 16;     bn[ci][j] = min(bn[ci][j], t * t + 1u);
            t = (&u2.x)[j] & 0xffffu; bp[ci][j] = min(bp[ci][j], t * t + 4u);
            t = (&u2.x)[j] >> 16;     bn[ci][j] = min(bn[ci][j], t * t + 4u);
            t = (&d2.x)[j] & 0xffffu; bp[ci][j] = min(bp[ci][j], t * t + 4u);
            t = (&d2.x)[j] >> 16;     bn[ci][j] = min(bn[ci][j], t * t + 4u);
        }
    }

    // ---- phase 3: rare serial tails, per class ----
    #pragma unroll
    for (int ci = 0; ci < NCL; ci++) {
        unsigned int bmax = 0u;
        #pragma unroll
        for (int j = 0; j < 4; j++) bmax = max(bmax, max(bp[ci][j], bn[ci][j]));
        #pragma unroll 1
        for (int d = 3; (unsigned int)(d * d) < bmax; ++d) {
            const uint4 wu = *reinterpret_cast<const uint4*>(col[ci] + max(r - d, 0) * WW);
            const uint4 wd = *reinterpret_cast<const uint4*>(col[ci] + min(r + d, HH - 1) * WW);
            unsigned int dd = (unsigned int)(d * d);
            bmax = 0u;
            #pragma unroll
            for (int j = 0; j < 4; j++) {
                unsigned int t;
                t = (&wu.x)[j] & 0xffffu; bp[ci][j] = min(bp[ci][j], t * t + dd);
                t = (&wu.x)[j] >> 16;     bn[ci][j] = min(bn[ci][j], t * t + dd);
                t = (&wd.x)[j] & 0xffffu; bp[ci][j] = min(bp[ci][j], t * t + dd);
                t = (&wd.x)[j] >> 16;     bn[ci][j] = min(bn[ci][j], t * t + dd);
                bmax = max(bmax, max(bp[ci][j], bn[ci][j]));
            }
        }
    }

    // ---- accumulate ----
    float acc = 0.0f;
    #pragma unroll
    for (int ci = 0; ci < NCL; ci++)
        #pragma unroll
        for (int j = 0; j < 4; j++)
            acc += prob[ci][j] * (sqrtf((float)bn[ci][j]) - sqrtf((float)bp[ci][j]));
    double local = (double)acc;

    // ---- block reduction (double) + tail finalize ----
    __shared__ double warp_sums[8];
    __shared__ bool is_last;
    const unsigned FULL = 0xffffffffu;
    #pragma unroll
    for (int off = 16; off > 0; off >>= 1)
        local += __shfl_down_sync(FULL, local, off);
    const int lane = threadIdx.x & 31;
    const int wid = threadIdx.x >> 5;
    if (lane == 0) warp_sums[wid] = local;
    __syncthreads();
    if (wid == 0) {
        double v = (lane < 8) ? warp_sums[lane] : 0.0;
        #pragma unroll
        for (int off = 4; off > 0; off >>= 1)
            v += __shfl_down_sync(FULL, v, off);
        if (lane == 0) {
            atomicAdd(&g_acc, v);
            __threadfence();
            unsigned int t = atomicAdd(&g_count, 1u);
            is_last = (t == gridDim.x - 1);
        }
    }
    __syncthreads();
    // Last block finalizes and restores all device state (deterministic replay)
    if (is_last) {
        if (threadIdx.x == 0) {
            __threadfence();
            double total = g_acc;
            // mean over N*C*H*W = 2*4*512*512 = 2^21 elements
            out[0] = (float)(total * (1.0 / 2097152.0));
            g_acc = 0.0;
            g_count = 0u;
        }
        if (threadIdx.x < NPRES) g_present[threadIdx.x] = 0;
    }
}

extern "C" void kernel_launch(void* const* d_in, const int* in_sizes, int n_in,
                              void* d_out, int out_size) {
    const float* logits = (const float*)d_in[0];     // [2,4,512,512] fp32
    const int* tgt_words = (const int*)d_in[1];      // [2,512,512] int32 or int64
    float* out = (float*)d_out;

    row_pass<<<NB * HH, 192>>>(tgt_words);

    // PDL launch: loss_pass may begin (softmax prologue) while row_pass drains;
    // cudaGridDependencySynchronize() inside orders the dependent reads.
    cudaLaunchConfig_t cfg = {};
    cfg.gridDim = dim3(NPIX / 1024, 1, 1);
    cfg.blockDim = dim3(256, 1, 1);
    cudaLaunchAttribute attr[1];
    attr[0].id = cudaLaunchAttributeProgrammaticStreamSerialization;
    attr[0].val.programmaticStreamSerializationAllowed = 1;
    cfg.attrs = attr;
    cfg.numAttrs = 1;
    cudaLaunchKernelEx(&cfg, loss_pass, logits, out);
}